// round 12
// baseline (speedup 1.0000x reference)
#include <cuda_runtime.h>
#include <cstdint>

#define B_  8
#define T_  2048
#define E_  1024
#define H_  64
#define BT_ (B_ * T_)

typedef unsigned int u32;
typedef unsigned short u16;

// fp16 scratch (static device arrays; no runtime alloc)
__device__ u16 g_w16[3 * E_ * H_];   // W fp16 [m][e][n]
__device__ u16 g_q16[BT_ * H_];      // [t][h] (scaled log2e/32)
__device__ u16 g_k16[BT_ * H_];      // [b][h][t] (transposed)
__device__ u16 g_v16[BT_ * H_];      // [t][h]

// ---------------------------------------------------------------------------
__device__ __forceinline__ u32 smem_u32(const void* p) {
    u32 a;
    asm("{ .reg .u64 t; cvta.to.shared.u64 t, %1; cvt.u32.u64 %0, t; }"
        : "=r"(a) : "l"(p));
    return a;
}
__device__ __forceinline__ u32 swa(u32 base, int r, int c) {
    return base + r * 128 + (((c ^ (r & 7)) & 7) << 4);
}
__device__ __forceinline__ u32 cvt2h(float a, float b) {
    u32 r;
    asm("cvt.rn.f16x2.f32 %0, %1, %2;" : "=r"(r) : "f"(b), "f"(a));
    return r;
}
__device__ __forceinline__ u16 h16(float a) {
    u16 r;
    asm("cvt.rn.f16.f32 %0, %1;" : "=h"(r) : "f"(a));
    return r;
}
__device__ __forceinline__ u32 ex2h2(u32 s) {
    u32 d;
    asm("ex2.approx.f16x2 %0, %1;" : "=r"(d) : "r"(s));
    return d;
}
__device__ __forceinline__ float hsum2(u32 p) {
    float f;
    asm("{ .reg .b16 lo,hi; .reg .f32 a,b;\n\t"
        "mov.b32 {lo,hi}, %1; cvt.f32.f16 a, lo; cvt.f32.f16 b, hi;\n\t"
        "add.f32 %0, a, b; }" : "=f"(f) : "r"(p));
    return f;
}
__device__ __forceinline__ void ldsm4(u32& r0, u32& r1, u32& r2, u32& r3, u32 a) {
    asm volatile("ldmatrix.sync.aligned.m8n8.x4.shared.b16 {%0,%1,%2,%3}, [%4];"
                 : "=r"(r0), "=r"(r1), "=r"(r2), "=r"(r3) : "r"(a));
}
__device__ __forceinline__ void ldsm4t(u32& r0, u32& r1, u32& r2, u32& r3, u32 a) {
    asm volatile("ldmatrix.sync.aligned.m8n8.x4.trans.shared.b16 {%0,%1,%2,%3}, [%4];"
                 : "=r"(r0), "=r"(r1), "=r"(r2), "=r"(r3) : "r"(a));
}
__device__ __forceinline__ void mma16816(float* c, const u32* a, u32 b0, u32 b1) {
    asm volatile(
        "mma.sync.aligned.m16n8k16.row.col.f32.f16.f16.f32 "
        "{%0,%1,%2,%3}, {%4,%5,%6,%7}, {%8,%9}, {%0,%1,%2,%3};"
        : "+f"(c[0]), "+f"(c[1]), "+f"(c[2]), "+f"(c[3])
        : "r"(a[0]), "r"(a[1]), "r"(a[2]), "r"(a[3]), "r"(b0), "r"(b1));
}
__device__ __forceinline__ void cpa16(u32 s, const void* g) {
    asm volatile("cp.async.cg.shared.global [%0], [%1], 16;" :: "r"(s), "l"(g));
}
#define CP_COMMIT() asm volatile("cp.async.commit_group;" ::: "memory")
#define CP_WAIT0()  asm volatile("cp.async.wait_group 0;" ::: "memory")

// ---------------------------------------------------------------------------
// prep: vectorized fp32 -> fp16 W convert
// ---------------------------------------------------------------------------
__global__ void __launch_bounds__(256) prep_w_kernel(
    const float* __restrict__ Wk, const float* __restrict__ Wq,
    const float* __restrict__ Wv)
{
    int q = blockIdx.x * 256 + threadIdx.x;        // < 49152 quads
    int idx = q * 4;
    int m = idx >> 16;
    int rem = idx & 65535;
    const float* W = (m == 0) ? Wk : (m == 1) ? Wq : Wv;
    float4 v = *(const float4*)&W[rem];
    *(uint2*)&g_w16[idx] = make_uint2(cvt2h(v.x, v.y), cvt2h(v.z, v.w));
}

// ---------------------------------------------------------------------------
// projection: 64 rows/block, 256 threads (8 warps: mw 0..1 x nw 0..3),
// warp tile 32x48. 2 blocks/SM. buffers {X 8K, W 24K} x2.
// ---------------------------------------------------------------------------
#define PB_X 0
#define PB_W 8192
#define PB_SZ 32768
#define P_TOT (2 * PB_SZ)           // 65536

__global__ void __launch_bounds__(256, 2) proj_kernel(const float* __restrict__ x)
{
    extern __shared__ char smem[];
    const u32 sb = smem_u32(smem);
    const int tid = threadIdx.x;
    const int lane = tid & 31;
    const int wid = tid >> 5;
    const int mw = wid >> 2, nw = wid & 3;        // 2 x 4
    const int g = lane >> 2, tg = lane & 3;
    const int ln15 = lane & 15, l16 = lane >> 4;
    const int row0 = blockIdx.x * 64;

    float C[2][6][4];
#pragma unroll
    for (int mt = 0; mt < 2; mt++)
#pragma unroll
        for (int j = 0; j < 6; j++)
#pragma unroll
            for (int r = 0; r < 4; r++) C[mt][j][r] = 0.f;

    float4 xr[4];

    // prologue
#pragma unroll
    for (int i = 0; i < 4; i++) {
        int idx = tid + i * 256;
        int r = idx >> 4, q4 = idx & 15;
        xr[i] = *(const float4*)&x[(size_t)(row0 + r) * E_ + q4 * 4];
    }
#pragma unroll
    for (int i = 0; i < 6; i++) {
        int idx = tid + i * 256;
        int mat = idx >> 9;
        int rem = idx & 511;
        int r = rem >> 3, c8 = rem & 7;
        const u16* src = g_w16 + (size_t)mat * 65536 + r * 64 + c8 * 8;
        cpa16(sb + PB_W + mat * 8192 + swa(0, r, c8), src);
    }
    CP_COMMIT();

    for (int c = 0; c < 16; c++) {
        const u32 buf = sb + (c & 1) * PB_SZ;

#pragma unroll
        for (int i = 0; i < 4; i++) {
            int idx = tid + i * 256;
            int r = idx >> 4, q4 = idx & 15;
            u32 hA = cvt2h(xr[i].x, xr[i].y);
            u32 hB = cvt2h(xr[i].z, xr[i].w);
            u32 off = swa(0, r, q4 >> 1) + 8 * (q4 & 1);
            *(uint2*)(smem + (c & 1) * PB_SZ + PB_X + off) = make_uint2(hA, hB);
        }
        CP_WAIT0();
        __syncthreads();

        if (c < 15) {
            const int k1 = (c + 1) * 64;
#pragma unroll
            for (int i = 0; i < 4; i++) {
                int idx = tid + i * 256;
                int r = idx >> 4, q4 = idx & 15;
                xr[i] = *(const float4*)&x[(size_t)(row0 + r) * E_ + k1 + q4 * 4];
            }
            const u32 nb = ((c + 1) & 1) * PB_SZ;
#pragma unroll
            for (int i = 0; i < 6; i++) {
                int idx = tid + i * 256;
                int mat = idx >> 9;
                int rem = idx & 511;
                int r = rem >> 3, c8 = rem & 7;
                const u16* src = g_w16 + (size_t)mat * 65536 + (k1 + r) * 64 + c8 * 8;
                cpa16(sb + nb + PB_W + mat * 8192 + swa(0, r, c8), src);
            }
            CP_COMMIT();
        }

#pragma unroll
        for (int ks = 0; ks < 4; ks++) {
            u32 a0[4], a1[4];
            ldsm4(a0[0], a0[1], a0[2], a0[3],
                  swa(buf + PB_X, 32 * mw + ln15, 2 * ks + l16));
            ldsm4(a1[0], a1[1], a1[2], a1[3],
                  swa(buf + PB_X, 32 * mw + 16 + ln15, 2 * ks + l16));
#pragma unroll
            for (int gi = 0; gi < 3; gi++) {
                int colg = nw * 48 + gi * 16;
                int mat = colg >> 6, ln = colg & 63;
                u32 b0, b1, b2, b3;
                ldsm4t(b0, b1, b2, b3,
                       swa(buf + PB_W + mat * 8192, 16 * ks + ln15, (ln >> 3) + l16));
                mma16816(C[0][2 * gi],     a0, b0, b1);
                mma16816(C[0][2 * gi + 1], a0, b2, b3);
                mma16816(C[1][2 * gi],     a1, b0, b1);
                mma16816(C[1][2 * gi + 1], a1, b2, b3);
            }
        }
    }

    // epilogue
    {
        const float QSC = 0.045084219770295f;   // 2^-5 * log2(e)
#pragma unroll
        for (int mt = 0; mt < 2; mt++) {
            int tok = row0 + 32 * mw + 16 * mt + g;
            int bB = tok >> 11, tl = tok & 2047;
#pragma unroll
            for (int j = 0; j < 6; j++) {
                int colg = nw * 48 + j * 8 + 2 * tg;
                int mat = colg >> 6, h = colg & 63;
                float v0 = C[mt][j][0], v1 = C[mt][j][1];
                float v2 = C[mt][j][2], v3 = C[mt][j][3];
                if (mat == 0) {
                    size_t o0 = ((size_t)bB * 64 + h) * 2048 + tl;
                    size_t o1 = ((size_t)bB * 64 + h + 1) * 2048 + tl;
                    g_k16[o0]     = h16(v0); g_k16[o1]     = h16(v1);
                    g_k16[o0 + 8] = h16(v2); g_k16[o1 + 8] = h16(v3);
                } else if (mat == 1) {
                    *(u32*)&g_q16[(size_t)tok * 64 + h] = cvt2h(v0 * QSC, v1 * QSC);
                    *(u32*)&g_q16[(size_t)(tok + 8) * 64 + h] = cvt2h(v2 * QSC, v3 * QSC);
                } else {
                    *(u32*)&g_v16[(size_t)tok * 64 + h] = cvt2h(v0, v1);
                    *(u32*)&g_v16[(size_t)(tok + 8) * 64 + h] = cvt2h(v2, v3);
                }
            }
        }
    }
}

// ---------------------------------------------------------------------------
// attention: 256 threads, 8 warps = 2 mw (32 q-rows) x 4 nw (16 kv-cols).
// ldsm K+V traffic halved vs 4x2. One q-tile (64) per block, KV macro 128.
// grid 256, 2 blocks/SM, big+small interleave. 2-round cross-nw reduction.
// ---------------------------------------------------------------------------
#define A_Q   0
#define A_BUF 8192
#define A_BSZ 32768
#define A_TOT (A_BUF + 2 * A_BSZ)   // 73728
#define A_REDA A_BUF                // 64x68 f32 = 17408
#define A_REDB (A_BUF + 17408)      // second partial array
#define A_LP2 0
#define A_LP3 1024
#define A_LP1 2048

__global__ void __launch_bounds__(256, 2) attn_kernel(float* __restrict__ out)
{
    extern __shared__ char smem[];
    const u32 sb = smem_u32(smem);
    const int tid = threadIdx.x;
    const int lane = tid & 31;
    const int wid = tid >> 5;
    const int mw = wid >> 2, nw = wid & 3;    // 2 x 4
    const int g = lane >> 2, tg = lane & 3;
    const int ln15 = lane & 15, l16 = lane >> 4;
    const int bid = blockIdx.x;
    const int qt = (bid < 128) ? (31 - (bid >> 3)) : ((bid - 128) >> 3);
    const int b  = bid & 7;
    const int q0 = qt * 64;
    const int kvend = q0 + 64;
    const int nt = (qt + 2) >> 1;               // 128-kv macro tiles

    const u16* Kg = g_k16 + (size_t)b * 64 * 2048;
    const u16* Vg = g_v16 + (size_t)b * 2048 * 64;

    // load Q (fp16, log2e-folded)
#pragma unroll
    for (int i = 0; i < 2; i++) {
        int idx = tid + i * 256;
        int r = idx >> 3, c8 = idx & 7;
        const u16* src = g_q16 + (size_t)(b * 2048 + q0 + r) * 64 + c8 * 8;
        uint4 v = *(const uint4*)src;
        *(uint4*)(smem + A_Q + swa(0, r, c8)) = v;
    }

    // prologue: async macro-tile 0
#pragma unroll
    for (int i = 0; i < 8; i++) {
        int idx = tid + i * 256;
        int arr = idx >> 9;
        int rem = idx & 511;
        int r = rem >> 3, c8 = rem & 7;
        const u16* src;
        u32 dst = A_BUF;
        if (arr < 2) { src = Kg + (size_t)r * 2048 + arr * 64 + c8 * 8; dst += arr * 8192; }
        else { int s = arr - 2; src = Vg + (size_t)(s * 64 + r) * 64 + c8 * 8; dst += 16384 + s * 8192; }
        cpa16(sb + swa(dst, r, c8), src);
    }
    CP_COMMIT();

    float O[2][8][4];
    float l[4] = {0.f, 0.f, 0.f, 0.f};
#pragma unroll
    for (int mt = 0; mt < 2; mt++)
#pragma unroll
        for (int j = 0; j < 8; j++)
#pragma unroll
            for (int r = 0; r < 4; r++) O[mt][j][r] = 0.f;

    u32 qf[2][4][4];
    bool qloaded = false;

    for (int t = 0; t < nt; t++) {
        CP_WAIT0();
        __syncthreads();

        if (t + 1 < nt) {
            const int kvn = (t + 1) * 128;
            const u32 bufn = A_BUF + ((t + 1) & 1) * A_BSZ;
#pragma unroll
            for (int i = 0; i < 8; i++) {
                int idx = tid + i * 256;
                int arr = idx >> 9;
                int rem = idx & 511;
                int r = rem >> 3, c8 = rem & 7;
                const u16* src;
                u32 dst = bufn;
                if (arr < 2) { src = Kg + (size_t)r * 2048 + kvn + arr * 64 + c8 * 8; dst += arr * 8192; }
                else { int s = arr - 2; src = Vg + (size_t)(kvn + s * 64 + r) * 64 + c8 * 8; dst += 16384 + s * 8192; }
                cpa16(sb + swa(dst, r, c8), src);
            }
            CP_COMMIT();
        }

        if (!qloaded) {
            qloaded = true;
#pragma unroll
            for (int mt = 0; mt < 2; mt++)
#pragma unroll
                for (int ks = 0; ks < 4; ks++)
                    ldsm4(qf[mt][ks][0], qf[mt][ks][1], qf[mt][ks][2], qf[mt][ks][3],
                          swa(sb + A_Q, 32 * mw + 16 * mt + ln15, 2 * ks + l16));
        }

        const u32 buf = sb + A_BUF + (t & 1) * A_BSZ;

#pragma unroll
        for (int sub = 0; sub < 2; sub++) {
            const int kv0 = t * 128 + sub * 64;
            if (kv0 >= kvend) break;
            const u32 KT = buf + sub * 8192;
            const u32 VT = buf + 16384 + sub * 8192;

            // S 32x16: frags [2mt+jn]
            float S[4][4];
#pragma unroll
            for (int f = 0; f < 4; f++)
#pragma unroll
                for (int r = 0; r < 4; r++) S[f][r] = 0.f;
#pragma unroll
            for (int ks = 0; ks < 4; ks++) {
                u32 b0, b1, b2, b3;
                ldsm4t(b0, b1, b2, b3,
                       swa(KT, 16 * ks + ln15, 2 * nw + l16));
                mma16816(S[0], qf[0][ks], b0, b1);
                mma16816(S[1], qf[0][ks], b2, b3);
                mma16816(S[2], qf[1][ks], b0, b1);
                mma16816(S[3], qf[1][ks], b2, b3);
            }

            // exp + mask + l; build P A-frags (m32 k16 -> 2 mt frags)
            const bool diag = (kv0 == q0);
            u32 ph[2][4];
#pragma unroll
            for (int mt = 0; mt < 2; mt++) {
                int rl = 32 * mw + 16 * mt + g;
#pragma unroll
                for (int jn = 0; jn < 2; jn++) {
                    int f = 2 * mt + jn;
                    int col0 = nw * 16 + 8 * jn + 2 * tg;
                    u32 p0 = ex2h2(cvt2h(S[f][0], S[f][1]));   // row rl
                    u32 p1 = ex2h2(cvt2h(S[f][2], S[f][3]));   // row rl+8
                    if (diag) {
                        u32 m0 = (col0 <= rl ? 0xFFFFu : 0u) | (col0 + 1 <= rl ? 0xFFFF0000u : 0u);
                        u32 m1 = (col0 <= rl + 8 ? 0xFFFFu : 0u) | (col0 + 1 <= rl + 8 ? 0xFFFF0000u : 0u);
                        p0 &= m0;
                        p1 &= m1;
                    }
                    l[2 * mt]     += hsum2(p0);
                    l[2 * mt + 1] += hsum2(p1);
                    ph[mt][jn * 2]     = p0;
                    ph[mt][jn * 2 + 1] = p1;
                }
            }

            // O += P @ V over warp's 16 kv rows
            {
                int vr = nw * 16 + ln15;
#pragma unroll
                for (int gh = 0; gh < 4; gh++) {
                    u32 b0, b1, b2, b3;
                    ldsm4t(b0, b1, b2, b3, swa(VT, vr, 2 * gh + l16));
                    mma16816(O[0][2 * gh],     ph[0], b0, b1);
                    mma16816(O[0][2 * gh + 1], ph[0], b2, b3);
                    mma16816(O[1][2 * gh],     ph[1], b0, b1);
                    mma16816(O[1][2 * gh + 1], ph[1], b2, b3);
                }
            }
        }
    }

    __syncthreads();                  // compute done before scratch reuse

    // reduce l across 4 tg lanes sharing each row
#pragma unroll
    for (int i = 0; i < 4; i++) {
        l[i] += __shfl_xor_sync(0xffffffffu, l[i], 1);
        l[i] += __shfl_xor_sync(0xffffffffu, l[i], 2);
    }

    float* REDA = (float*)(smem + A_REDA);
    float* REDB = (float*)(smem + A_REDB);
    float* LP2  = (float*)(smem + A_LP2);
    float* LP3  = (float*)(smem + A_LP3);
    float* LP1  = (float*)(smem + A_LP1);
    const int rA = 32 * mw + g;       // rows rA, rA+8 (mt0); rA+16, rA+24 (mt1)

    // round 1: nw 2,3 publish
    if (nw >= 2) {
        float* RED = (nw == 2) ? REDA : REDB;
        float* LP  = (nw == 2) ? LP2 : LP3;
#pragma unroll
        for (int mt = 0; mt < 2; mt++)
#pragma unroll
            for (int j = 0; j < 8; j++) {
                int col = 8 * j + 2 * tg;
                int r0 = rA + 16 * mt;
                RED[r0 * 68 + col]           = O[mt][j][0];
                RED[r0 * 68 + col + 1]       = O[mt][j][1];
                RED[(r0 + 8) * 68 + col]     = O[mt][j][2];
                RED[(r0 + 8) * 68 + col + 1] = O[mt][j][3];
            }
        if (tg == 0) {
            LP[rA] = l[0]; LP[rA + 8] = l[1];
            LP[rA + 16] = l[2]; LP[rA + 24] = l[3];
        }
    }
    __syncthreads();
    if (nw < 2) {
        float* RED = (nw == 0) ? REDA : REDB;
        float* LP  = (nw == 0) ? LP2 : LP3;
#pragma unroll
        for (int mt = 0; mt < 2; mt++)
#pragma unroll
            for (int j = 0; j < 8; j++) {
                int col = 8 * j + 2 * tg;
                int r0 = rA + 16 * mt;
                O[mt][j][0] += RED[r0 * 68 + col];
                O[mt][j][1] += RED[r0 * 68 + col + 1];
                O[mt][j][2] += RED[(r0 + 8) * 68 + col];
                O[mt][j][3] += RED[(r0 + 8) * 68 + col + 1];
            }
        l[0] += LP[rA]; l[1] += LP[rA + 8];
        l[2] += LP[rA + 16]; l[3] += LP[rA + 24];
    }
    __syncthreads();
    // round 2: nw 1 publishes combined partial
    if (nw == 1) {
#pragma unroll
        for (int mt = 0; mt < 2; mt++)
#pragma unroll
            for (int j = 0; j < 8; j++) {
                int col = 8 * j + 2 * tg;
                int r0 = rA + 16 * mt;
                REDA[r0 * 68 + col]           = O[mt][j][0];
                REDA[r0 * 68 + col + 1]       = O[mt][j][1];
                REDA[(r0 + 8) * 68 + col]     = O[mt][j][2];
                REDA[(r0 + 8) * 68 + col + 1] = O[mt][j][3];
            }
        if (tg == 0) {
            LP1[rA] = l[0]; LP1[rA + 8] = l[1];
            LP1[rA + 16] = l[2]; LP1[rA + 24] = l[3];
        }
    }
    __syncthreads();
    if (nw == 0) {
        float inv[4];
        inv[0] = 1.f / (l[0] + LP1[rA]);
        inv[1] = 1.f / (l[1] + LP1[rA + 8]);
        inv[2] = 1.f / (l[2] + LP1[rA + 16]);
        inv[3] = 1.f / (l[3] + LP1[rA + 24]);
#pragma unroll
        for (int mt = 0; mt < 2; mt++) {
            int r0 = rA + 16 * mt;
            float* Oa = out + ((size_t)b * T_ + q0 + r0) * H_;
            float* Ob = Oa + 8 * H_;
#pragma unroll
            for (int j = 0; j < 8; j++) {
                int col = 8 * j + 2 * tg;
                *(float2*)&Oa[col] = make_float2(
                    (O[mt][j][0] + REDA[r0 * 68 + col]) * inv[2 * mt],
                    (O[mt][j][1] + REDA[r0 * 68 + col + 1]) * inv[2 * mt]);
                *(float2*)&Ob[col] = make_float2(
                    (O[mt][j][2] + REDA[(r0 + 8) * 68 + col]) * inv[2 * mt + 1],
                    (O[mt][j][3] + REDA[(r0 + 8) * 68 + col + 1]) * inv[2 * mt + 1]);
            }
        }
    }
}

// ---------------------------------------------------------------------------
extern "C" void kernel_launch(void* const* d_in, const int* in_sizes, int n_in,
                              void* d_out, int out_size)
{
    const float* x  = (const float*)d_in[0];
    const float* Wk = (const float*)d_in[1];
    const float* Wq = (const float*)d_in[2];
    const float* Wv = (const float*)d_in[3];
    float* out = (float*)d_out;
    (void)in_sizes; (void)n_in; (void)out_size;

    cudaFuncSetAttribute(proj_kernel,
                         cudaFuncAttributeMaxDynamicSharedMemorySize, P_TOT);
    cudaFuncSetAttribute(attn_kernel,
                         cudaFuncAttributeMaxDynamicSharedMemorySize, A_TOT);

    prep_w_kernel<<<192, 256>>>(Wk, Wq, Wv);
    proj_kernel<<<BT_ / 64, 256, P_TOT>>>(x);
    attn_kernel<<<256, 256, A_TOT>>>(out);
}

// round 13
// speedup vs baseline: 1.1784x; 1.1784x over previous
#include <cuda_runtime.h>
#include <cstdint>

#define B_  8
#define T_  2048
#define E_  1024
#define H_  64
#define BT_ (B_ * T_)

typedef unsigned int u32;
typedef unsigned short u16;

// fp16 scratch (static device arrays; no runtime alloc)
__device__ u16 g_w16[3 * E_ * H_];   // W fp16 [m][e][n]
__device__ u16 g_q16[BT_ * H_];      // [t][h] (scaled log2e/32)
__device__ u16 g_k16[BT_ * H_];      // [b][h][t] (transposed)
__device__ u16 g_v16[BT_ * H_];      // [t][h]

// ---------------------------------------------------------------------------
__device__ __forceinline__ u32 smem_u32(const void* p) {
    u32 a;
    asm("{ .reg .u64 t; cvta.to.shared.u64 t, %1; cvt.u32.u64 %0, t; }"
        : "=r"(a) : "l"(p));
    return a;
}
__device__ __forceinline__ u32 swa(u32 base, int r, int c) {
    return base + r * 128 + (((c ^ (r & 7)) & 7) << 4);
}
__device__ __forceinline__ u32 cvt2h(float a, float b) {
    u32 r;
    asm("cvt.rn.f16x2.f32 %0, %1, %2;" : "=r"(r) : "f"(b), "f"(a));
    return r;
}
__device__ __forceinline__ u16 h16(float a) {
    u16 r;
    asm("cvt.rn.f16.f32 %0, %1;" : "=h"(r) : "f"(a));
    return r;
}
__device__ __forceinline__ u32 ex2h2(u32 s) {
    u32 d;
    asm("ex2.approx.f16x2 %0, %1;" : "=r"(d) : "r"(s));
    return d;
}
__device__ __forceinline__ float hsum2(u32 p) {
    float f;
    asm("{ .reg .b16 lo,hi; .reg .f32 a,b;\n\t"
        "mov.b32 {lo,hi}, %1; cvt.f32.f16 a, lo; cvt.f32.f16 b, hi;\n\t"
        "add.f32 %0, a, b; }" : "=f"(f) : "r"(p));
    return f;
}
__device__ __forceinline__ void ldsm4(u32& r0, u32& r1, u32& r2, u32& r3, u32 a) {
    asm volatile("ldmatrix.sync.aligned.m8n8.x4.shared.b16 {%0,%1,%2,%3}, [%4];"
                 : "=r"(r0), "=r"(r1), "=r"(r2), "=r"(r3) : "r"(a));
}
__device__ __forceinline__ void ldsm4t(u32& r0, u32& r1, u32& r2, u32& r3, u32 a) {
    asm volatile("ldmatrix.sync.aligned.m8n8.x4.trans.shared.b16 {%0,%1,%2,%3}, [%4];"
                 : "=r"(r0), "=r"(r1), "=r"(r2), "=r"(r3) : "r"(a));
}
__device__ __forceinline__ void mma16816(float* c, const u32* a, u32 b0, u32 b1) {
    asm volatile(
        "mma.sync.aligned.m16n8k16.row.col.f32.f16.f16.f32 "
        "{%0,%1,%2,%3}, {%4,%5,%6,%7}, {%8,%9}, {%0,%1,%2,%3};"
        : "+f"(c[0]), "+f"(c[1]), "+f"(c[2]), "+f"(c[3])
        : "r"(a[0]), "r"(a[1]), "r"(a[2]), "r"(a[3]), "r"(b0), "r"(b1));
}
__device__ __forceinline__ void cpa16(u32 s, const void* g) {
    asm volatile("cp.async.cg.shared.global [%0], [%1], 16;" :: "r"(s), "l"(g));
}
#define CP_COMMIT() asm volatile("cp.async.commit_group;" ::: "memory")
#define CP_WAIT0()  asm volatile("cp.async.wait_group 0;" ::: "memory")
#define CP_WAIT1()  asm volatile("cp.async.wait_group 1;" ::: "memory")

// ---------------------------------------------------------------------------
// prep: vectorized fp32 -> fp16 W convert, ILP=2
// ---------------------------------------------------------------------------
__global__ void __launch_bounds__(256) prep_w_kernel(
    const float* __restrict__ Wk, const float* __restrict__ Wq,
    const float* __restrict__ Wv)
{
    int q = blockIdx.x * 256 + threadIdx.x;        // < 24576
#pragma unroll
    for (int i = 0; i < 2; i++) {
        int idx = (q + i * 24576) * 4;
        int m = idx >> 16;
        int rem = idx & 65535;
        const float* W = (m == 0) ? Wk : (m == 1) ? Wq : Wv;
        float4 v = *(const float4*)&W[rem];
        *(uint2*)&g_w16[idx] = make_uint2(cvt2h(v.x, v.y), cvt2h(v.z, v.w));
    }
}

// ---------------------------------------------------------------------------
// projection: 64 rows/block, 256 threads (8 warps: mw 0..1 x nw 0..3),
// warp tile 32x48. 2 blocks/SM. buffers {X 8K, W 24K} x2.
// ---------------------------------------------------------------------------
#define PB_X 0
#define PB_W 8192
#define PB_SZ 32768
#define P_TOT (2 * PB_SZ)           // 65536

__global__ void __launch_bounds__(256, 2) proj_kernel(const float* __restrict__ x)
{
    extern __shared__ char smem[];
    const u32 sb = smem_u32(smem);
    const int tid = threadIdx.x;
    const int lane = tid & 31;
    const int wid = tid >> 5;
    const int mw = wid >> 2, nw = wid & 3;        // 2 x 4
    const int g = lane >> 2, tg = lane & 3;
    const int ln15 = lane & 15, l16 = lane >> 4;
    const int row0 = blockIdx.x * 64;

    float C[2][6][4];
#pragma unroll
    for (int mt = 0; mt < 2; mt++)
#pragma unroll
        for (int j = 0; j < 6; j++)
#pragma unroll
            for (int r = 0; r < 4; r++) C[mt][j][r] = 0.f;

    float4 xr[4];

    // prologue
#pragma unroll
    for (int i = 0; i < 4; i++) {
        int idx = tid + i * 256;
        int r = idx >> 4, q4 = idx & 15;
        xr[i] = *(const float4*)&x[(size_t)(row0 + r) * E_ + q4 * 4];
    }
#pragma unroll
    for (int i = 0; i < 6; i++) {
        int idx = tid + i * 256;
        int mat = idx >> 9;
        int rem = idx & 511;
        int r = rem >> 3, c8 = rem & 7;
        const u16* src = g_w16 + (size_t)mat * 65536 + r * 64 + c8 * 8;
        cpa16(sb + PB_W + mat * 8192 + swa(0, r, c8), src);
    }
    CP_COMMIT();

    for (int c = 0; c < 16; c++) {
        const u32 buf = sb + (c & 1) * PB_SZ;

#pragma unroll
        for (int i = 0; i < 4; i++) {
            int idx = tid + i * 256;
            int r = idx >> 4, q4 = idx & 15;
            u32 hA = cvt2h(xr[i].x, xr[i].y);
            u32 hB = cvt2h(xr[i].z, xr[i].w);
            u32 off = swa(0, r, q4 >> 1) + 8 * (q4 & 1);
            *(uint2*)(smem + (c & 1) * PB_SZ + PB_X + off) = make_uint2(hA, hB);
        }
        CP_WAIT0();
        __syncthreads();

        if (c < 15) {
            const int k1 = (c + 1) * 64;
#pragma unroll
            for (int i = 0; i < 4; i++) {
                int idx = tid + i * 256;
                int r = idx >> 4, q4 = idx & 15;
                xr[i] = *(const float4*)&x[(size_t)(row0 + r) * E_ + k1 + q4 * 4];
            }
            const u32 nb = ((c + 1) & 1) * PB_SZ;
#pragma unroll
            for (int i = 0; i < 6; i++) {
                int idx = tid + i * 256;
                int mat = idx >> 9;
                int rem = idx & 511;
                int r = rem >> 3, c8 = rem & 7;
                const u16* src = g_w16 + (size_t)mat * 65536 + (k1 + r) * 64 + c8 * 8;
                cpa16(sb + nb + PB_W + mat * 8192 + swa(0, r, c8), src);
            }
            CP_COMMIT();
        }

#pragma unroll
        for (int ks = 0; ks < 4; ks++) {
            u32 a0[4], a1[4];
            ldsm4(a0[0], a0[1], a0[2], a0[3],
                  swa(buf + PB_X, 32 * mw + ln15, 2 * ks + l16));
            ldsm4(a1[0], a1[1], a1[2], a1[3],
                  swa(buf + PB_X, 32 * mw + 16 + ln15, 2 * ks + l16));
#pragma unroll
            for (int gi = 0; gi < 3; gi++) {
                int colg = nw * 48 + gi * 16;
                int mat = colg >> 6, ln = colg & 63;
                u32 b0, b1, b2, b3;
                ldsm4t(b0, b1, b2, b3,
                       swa(buf + PB_W + mat * 8192, 16 * ks + ln15, (ln >> 3) + l16));
                mma16816(C[0][2 * gi],     a0, b0, b1);
                mma16816(C[0][2 * gi + 1], a0, b2, b3);
                mma16816(C[1][2 * gi],     a1, b0, b1);
                mma16816(C[1][2 * gi + 1], a1, b2, b3);
            }
        }
    }

    // epilogue
    {
        const float QSC = 0.045084219770295f;   // 2^-5 * log2(e)
#pragma unroll
        for (int mt = 0; mt < 2; mt++) {
            int tok = row0 + 32 * mw + 16 * mt + g;
            int bB = tok >> 11, tl = tok & 2047;
#pragma unroll
            for (int j = 0; j < 6; j++) {
                int colg = nw * 48 + j * 8 + 2 * tg;
                int mat = colg >> 6, h = colg & 63;
                float v0 = C[mt][j][0], v1 = C[mt][j][1];
                float v2 = C[mt][j][2], v3 = C[mt][j][3];
                if (mat == 0) {
                    size_t o0 = ((size_t)bB * 64 + h) * 2048 + tl;
                    size_t o1 = ((size_t)bB * 64 + h + 1) * 2048 + tl;
                    g_k16[o0]     = h16(v0); g_k16[o1]     = h16(v1);
                    g_k16[o0 + 8] = h16(v2); g_k16[o1 + 8] = h16(v3);
                } else if (mat == 1) {
                    *(u32*)&g_q16[(size_t)tok * 64 + h] = cvt2h(v0 * QSC, v1 * QSC);
                    *(u32*)&g_q16[(size_t)(tok + 8) * 64 + h] = cvt2h(v2 * QSC, v3 * QSC);
                } else {
                    *(u32*)&g_v16[(size_t)tok * 64 + h] = cvt2h(v0, v1);
                    *(u32*)&g_v16[(size_t)(tok + 8) * 64 + h] = cvt2h(v2, v3);
                }
            }
        }
    }
}

// ---------------------------------------------------------------------------
// attention: 256 threads, 8 warps (mw 0..3 x nw 0..1), one q-tile (64) per
// block. KV macro-tile 128, TRIPLE-buffered (prefetch depth 2, wait_group 1).
// grid 256, 2 blocks/SM; big+small interleave. exp via ex2.approx.f16x2.
// smem: Q 8K + 3 x {Ksub0 8K, Ksub1 8K, Vsub0 8K, Vsub1 8K} = 104K
// ---------------------------------------------------------------------------
#define A_Q   0
#define A_BUF 8192
#define A_BSZ 32768
#define A_TOT (A_BUF + 3 * A_BSZ)   // 106496
#define A_RED A_BUF
#define A_LRED (A_BUF + 64 * 68 * 4)

__global__ void __launch_bounds__(256, 2) attn_kernel(float* __restrict__ out)
{
    extern __shared__ char smem[];
    const u32 sb = smem_u32(smem);
    const int tid = threadIdx.x;
    const int lane = tid & 31;
    const int wid = tid >> 5;
    const int mw = wid & 3, nw = wid >> 2;
    const int g = lane >> 2, tg = lane & 3;
    const int ln15 = lane & 15, l16 = lane >> 4;
    const int bid = blockIdx.x;
    const int qt = (bid < 128) ? (31 - (bid >> 3)) : ((bid - 128) >> 3);
    const int b  = bid & 7;
    const int q0 = qt * 64;
    const int kvend = q0 + 64;
    const int nt = (qt + 2) >> 1;               // 128-kv macro tiles

    const u16* Kg = g_k16 + (size_t)b * 64 * 2048;
    const u16* Vg = g_v16 + (size_t)b * 2048 * 64;

    // load Q (fp16, log2e-folded)
#pragma unroll
    for (int i = 0; i < 2; i++) {
        int idx = tid + i * 256;
        int r = idx >> 3, c8 = idx & 7;
        const u16* src = g_q16 + (size_t)(b * 2048 + q0 + r) * 64 + c8 * 8;
        uint4 v = *(const uint4*)src;
        *(uint4*)(smem + A_Q + swa(0, r, c8)) = v;
    }

    // helper lambda-ish macro body via plain code: issue macro-tile T into slot T%3
#define ISSUE_TILE(T)                                                          \
    {                                                                          \
        const int kvn = (T) * 128;                                             \
        const u32 bufn = A_BUF + ((T) % 3) * A_BSZ;                            \
        _Pragma("unroll")                                                      \
        for (int i = 0; i < 8; i++) {                                          \
            int idx = tid + i * 256;                                           \
            int arr = idx >> 9;                                                \
            int rem = idx & 511;                                               \
            int r = rem >> 3, c8 = rem & 7;                                    \
            const u16* src;                                                    \
            u32 dst = bufn;                                                    \
            if (arr < 2) { src = Kg + (size_t)r * 2048 + kvn + arr * 64 + c8 * 8; dst += arr * 8192; } \
            else { int s = arr - 2; src = Vg + (size_t)(kvn + s * 64 + r) * 64 + c8 * 8; dst += 16384 + s * 8192; } \
            cpa16(sb + swa(dst, r, c8), src);                                  \
        }                                                                      \
    }

    // prologue: tiles 0 and 1 (commit groups unconditionally to keep the
    // wait_group-1 invariant: group index == tile index)
    ISSUE_TILE(0);
    CP_COMMIT();
    if (nt > 1) ISSUE_TILE(1);
    CP_COMMIT();

    float S[4][4], O[8][4];
    float l0 = 0.f, l1 = 0.f;
#pragma unroll
    for (int j = 0; j < 8; j++)
#pragma unroll
        for (int r = 0; r < 4; r++) O[j][r] = 0.f;

    u32 qf[4][4];
    bool qloaded = false;

    for (int t = 0; t < nt; t++) {
        CP_WAIT1();               // tile t landed; tile t+1 may be in flight
        __syncthreads();          // slot (t+2)%3 free (its last reads were iter t-1)

        if (t + 2 < nt) ISSUE_TILE(t + 2);
        CP_COMMIT();              // unconditional: group t+2 (maybe empty)

        if (!qloaded) {
            qloaded = true;
#pragma unroll
            for (int ks = 0; ks < 4; ks++)
                ldsm4(qf[ks][0], qf[ks][1], qf[ks][2], qf[ks][3],
                      swa(sb + A_Q, 16 * mw + ln15, 2 * ks + l16));
        }

        const u32 buf = sb + A_BUF + (t % 3) * A_BSZ;

#pragma unroll
        for (int sub = 0; sub < 2; sub++) {
            const int kv0 = t * 128 + sub * 64;
            if (kv0 >= kvend) break;
            const u32 KT = buf + sub * 8192;
            const u32 VT = buf + 16384 + sub * 8192;

            // S slice 16x32 (kv cols nw*32..+31 within this 64-kv sub-tile)
#pragma unroll
            for (int j = 0; j < 4; j++)
#pragma unroll
                for (int r = 0; r < 4; r++) S[j][r] = 0.f;
#pragma unroll
            for (int ks = 0; ks < 4; ks++) {
#pragma unroll
                for (int p = 0; p < 2; p++) {
                    u32 b0, b1, b2, b3;
                    ldsm4t(b0, b1, b2, b3,
                           swa(KT, 16 * ks + ln15, nw * 4 + 2 * p + l16));
                    mma16816(S[2 * p],     qf[ks], b0, b1);
                    mma16816(S[2 * p + 1], qf[ks], b2, b3);
                }
            }

            // p = 2^s (f16x2); mask on diagonal sub-tile; accumulate l
            const bool diag = (kv0 == q0);
            const int rl0 = 16 * mw + g;
            u32 ph[2][4];
#pragma unroll
            for (int j = 0; j < 4; j++) {
                int col0 = nw * 32 + 8 * j + 2 * tg;
                u32 p0 = ex2h2(cvt2h(S[j][0], S[j][1]));
                u32 p1 = ex2h2(cvt2h(S[j][2], S[j][3]));
                if (diag) {
                    u32 m0 = (col0 <= rl0 ? 0xFFFFu : 0u) | (col0 + 1 <= rl0 ? 0xFFFF0000u : 0u);
                    u32 m1 = (col0 <= rl0 + 8 ? 0xFFFFu : 0u) | (col0 + 1 <= rl0 + 8 ? 0xFFFF0000u : 0u);
                    p0 &= m0;
                    p1 &= m1;
                }
                l0 += hsum2(p0);
                l1 += hsum2(p1);
                ph[j >> 1][(j & 1) * 2]     = p0;
                ph[j >> 1][(j & 1) * 2 + 1] = p1;
            }

            // O += P @ V over warp's 32 kv rows
#pragma unroll
            for (int ks = 0; ks < 2; ks++) {
                int vr = nw * 32 + 16 * ks + ln15;
#pragma unroll
                for (int gh = 0; gh < 4; gh++) {
                    u32 b0, b1, b2, b3;
                    ldsm4t(b0, b1, b2, b3, swa(VT, vr, 2 * gh + l16));
                    mma16816(O[2 * gh],     ph[ks], b0, b1);
                    mma16816(O[2 * gh + 1], ph[ks], b2, b3);
                }
            }
        }
    }

    __syncthreads();                  // compute done before scratch reuse

    // reduce l across 4 lanes sharing a row
    l0 += __shfl_xor_sync(0xffffffffu, l0, 1);
    l0 += __shfl_xor_sync(0xffffffffu, l0, 2);
    l1 += __shfl_xor_sync(0xffffffffu, l1, 1);
    l1 += __shfl_xor_sync(0xffffffffu, l1, 2);

    // cross-nw reduction via smem (aliases KV buffers)
    float* RED  = (float*)(smem + A_RED);
    float* LRED = (float*)(smem + A_LRED);
    const int r0 = 16 * mw + g;
    if (nw == 1) {
#pragma unroll
        for (int j = 0; j < 8; j++) {
            int col = 8 * j + 2 * tg;
            RED[r0 * 68 + col]           = O[j][0];
            RED[r0 * 68 + col + 1]       = O[j][1];
            RED[(r0 + 8) * 68 + col]     = O[j][2];
            RED[(r0 + 8) * 68 + col + 1] = O[j][3];
        }
        if (tg == 0) { LRED[r0] = l0; LRED[r0 + 8] = l1; }
    }
    __syncthreads();
    if (nw == 0) {
        float inv0 = 1.f / (l0 + LRED[r0]);
        float inv1 = 1.f / (l1 + LRED[r0 + 8]);
        float* O0 = out + ((size_t)b * T_ + q0 + r0) * H_;
        float* O1 = O0 + 8 * H_;
#pragma unroll
        for (int j = 0; j < 8; j++) {
            int col = 8 * j + 2 * tg;
            *(float2*)&O0[col] = make_float2(
                (O[j][0] + RED[r0 * 68 + col]) * inv0,
                (O[j][1] + RED[r0 * 68 + col + 1]) * inv0);
            *(float2*)&O1[col] = make_float2(
                (O[j][2] + RED[(r0 + 8) * 68 + col]) * inv1,
                (O[j][3] + RED[(r0 + 8) * 68 + col + 1]) * inv1);
        }
    }
#undef ISSUE_TILE
}

// ---------------------------------------------------------------------------
extern "C" void kernel_launch(void* const* d_in, const int* in_sizes, int n_in,
                              void* d_out, int out_size)
{
    const float* x  = (const float*)d_in[0];
    const float* Wk = (const float*)d_in[1];
    const float* Wq = (const float*)d_in[2];
    const float* Wv = (const float*)d_in[3];
    float* out = (float*)d_out;
    (void)in_sizes; (void)n_in; (void)out_size;

    cudaFuncSetAttribute(proj_kernel,
                         cudaFuncAttributeMaxDynamicSharedMemorySize, P_TOT);
    cudaFuncSetAttribute(attn_kernel,
                         cudaFuncAttributeMaxDynamicSharedMemorySize, A_TOT);

    prep_w_kernel<<<96, 256>>>(Wk, Wq, Wv);
    proj_kernel<<<BT_ / 64, 256, P_TOT>>>(x);
    attn_kernel<<<256, 256, A_TOT>>>(out);
}